// round 4
// baseline (speedup 1.0000x reference)
#include <cuda_runtime.h>

// Problem constants (fixed by the dataset)
#define NB_B 64
#define NB_N 20000
#define NB_E 1280000

// Scratch (device globals; no allocations allowed)
__device__ __align__(16) float g_xT[NB_N * NB_B];   // x transposed [N, B], 5.12MB (L2-resident)
__device__ int  g_cnt[NB_N];                        // per-dst degree (histogram)
__device__ int  g_off[NB_N + 1];                    // CSR row offsets
__device__ int  g_cur[NB_N];                        // scatter cursors
__device__ __align__(8) int2 g_edge[NB_E];          // CSR edges: (src, bits(adj*w)) grouped by dst

// ---------------------------------------------------------------------------
// Kernel 1: transpose x [B, N] -> g_xT [N, B]; zero the histogram.
// ---------------------------------------------------------------------------
__global__ void prep_kernel(const float* __restrict__ x) {
    __shared__ float tile[32][33];
    const int n0 = blockIdx.x * 32;
    const int b0 = blockIdx.y * 32;
    const int tx = threadIdx.x, ty = threadIdx.y;

    tile[ty][tx] = x[(b0 + ty) * NB_N + (n0 + tx)];

    if (blockIdx.y == 0 && ty == 0) g_cnt[n0 + tx] = 0;   // 625*32 = 20000
    __syncthreads();

    g_xT[(n0 + ty) * NB_B + (b0 + tx)] = tile[tx][ty];
}

// ---------------------------------------------------------------------------
// Kernel 2: histogram of dst (RED, no return value used)
// ---------------------------------------------------------------------------
__global__ void hist_kernel(const int* __restrict__ dst) {
    const int e = blockIdx.x * blockDim.x + threadIdx.x;
    if (e < NB_E) atomicAdd(&g_cnt[dst[e]], 1);
}

// ---------------------------------------------------------------------------
// Kernel 3: exclusive prefix sum over 20000 counts. Single block, 1024 thr.
// Each thread serially scans 20 elements; Hillis-Steele over thread totals.
// ---------------------------------------------------------------------------
__global__ void scan_kernel() {
    __shared__ int tsum[1024];
    const int t = threadIdx.x;

    int local[20];
    int s = 0;
    #pragma unroll
    for (int i = 0; i < 20; i++) {
        const int idx = t * 20 + i;
        const int v = (idx < NB_N) ? g_cnt[idx] : 0;
        local[i] = s;
        s += v;
    }
    tsum[t] = s;
    __syncthreads();

    for (int d = 1; d < 1024; d <<= 1) {
        const int v = (t >= d) ? tsum[t - d] : 0;
        __syncthreads();
        tsum[t] += v;
        __syncthreads();
    }

    const int base = (t > 0) ? tsum[t - 1] : 0;
    #pragma unroll
    for (int i = 0; i < 20; i++) {
        const int idx = t * 20 + i;
        if (idx < NB_N) {
            const int o = base + local[i];
            g_off[idx] = o;
            g_cur[idx] = o;
        }
    }
    if (t == 1023) g_off[NB_N] = tsum[1023];
}

// ---------------------------------------------------------------------------
// Kernel 4: scatter edges into CSR order (grouped by dst)
// ---------------------------------------------------------------------------
__global__ void scatter_kernel(const float* __restrict__ adj,
                               const float* __restrict__ w,
                               const int*   __restrict__ src,
                               const int*   __restrict__ dst) {
    const int e = blockIdx.x * blockDim.x + threadIdx.x;
    if (e >= NB_E) return;
    const int d = dst[e];
    const int pos = atomicAdd(&g_cur[d], 1);
    g_edge[pos] = make_int2(src[e], __float_as_int(adj[e] * w[e]));
}

// ---------------------------------------------------------------------------
// Kernel 5: CSR SpMM + fused epilogue. One warp per dst row.
// 32 lanes x float2 register accumulators; per-edge: 8B coalesced metadata
// (32 edges at a time, distributed over lanes, shfl-broadcast) + 256B gather.
// ---------------------------------------------------------------------------
__global__ void spmm_kernel(const float* __restrict__ x,
                            const float* __restrict__ self_w,
                            const float* __restrict__ bias,
                            float* __restrict__ out) {
    const int warp = (blockIdx.x * blockDim.x + threadIdx.x) >> 5;
    if (warp >= NB_N) return;
    const int lane = threadIdx.x & 31;
    const int r = warp;

    const int i0 = g_off[r];
    const int i1 = g_off[r + 1];

    float2 acc = make_float2(0.0f, 0.0f);

    for (int base = i0; base < i1; base += 32) {
        const int m = i1 - base;
        int2 e = make_int2(0, 0);
        if (lane < m) e = g_edge[base + lane];
        const int lim = (m < 32) ? m : 32;
        #pragma unroll 8
        for (int j = 0; j < lim; j++) {
            const int   sj = __shfl_sync(0xffffffffu, e.x, j);
            const float cj = __int_as_float(__shfl_sync(0xffffffffu, e.y, j));
            const float2 v = *reinterpret_cast<const float2*>(g_xT + sj * NB_B + lane * 2);
            acc.x = fmaf(cj, v.x, acc.x);
            acc.y = fmaf(cj, v.y, acc.y);
        }
    }

    // Fused epilogue: out[b][n] = relu(acc * x[0][n]*self_w[n] + bias[n])
    const float sl = x[r] * self_w[r];   // x row 0 (faithful reference quirk)
    const float bb = bias[r];
    const int b0 = lane * 2;
    out[(size_t)b0 * NB_N + r]       = fmaxf(fmaf(acc.x, sl, bb), 0.0f);
    out[(size_t)(b0 + 1) * NB_N + r] = fmaxf(fmaf(acc.y, sl, bb), 0.0f);
}

// ---------------------------------------------------------------------------
// Launch
// ---------------------------------------------------------------------------
extern "C" void kernel_launch(void* const* d_in, const int* in_sizes, int n_in,
                              void* d_out, int out_size) {
    const float* x      = (const float*)d_in[0];
    const float* adj    = (const float*)d_in[1];
    const float* w      = (const float*)d_in[2];
    const float* self_w = (const float*)d_in[3];
    const float* bias   = (const float*)d_in[4];
    const int*   src    = (const int*)d_in[5];
    const int*   dst    = (const int*)d_in[6];
    float* out = (float*)d_out;

    dim3 tb(32, 32);
    dim3 tg(NB_N / 32, NB_B / 32);   // (625, 2)
    prep_kernel<<<tg, tb>>>(x);

    const int eb = 256;
    const int eg = (NB_E + eb - 1) / eb;   // 5000
    hist_kernel<<<eg, eb>>>(dst);

    scan_kernel<<<1, 1024>>>();

    scatter_kernel<<<eg, eb>>>(adj, w, src, dst);

    // one warp per row: 20000 warps, 8 warps per block
    spmm_kernel<<<(NB_N + 7) / 8, 256>>>(x, self_w, bias, out);
}

// round 5
// speedup vs baseline: 1.2079x; 1.2079x over previous
#include <cuda_runtime.h>

// Problem constants (fixed by the dataset)
#define NB_B 64
#define NB_N 20000
#define NB_E 1280000

// src-range bucketing: bucket = src >> 7  (128 nodes => 32KB xT slice, L1-resident)
#define BUCK_SHIFT 7
#define NBUCK 157            // ceil(20000 / 128)
#define BUCK_CAP 10240       // mean count 8153, sigma ~90 -> 23 sigma headroom

// Scratch (device globals; no allocations allowed)
__device__ __align__(16) float g_xT[NB_N * NB_B];    // x^T [N, B], 5.12MB
__device__ __align__(16) float g_acc[NB_N * NB_B];   // accumulator [N, B], 5.12MB
__device__ int g_bcnt[NBUCK];                        // per-bucket edge counts / cursors
__device__ __align__(8) int2 g_ebuf[NBUCK * BUCK_CAP]; // bucketed edges: (src<<15|dst, coeff)

// ---------------------------------------------------------------------------
// Kernel 1: transpose x [B, N] -> g_xT [N, B]; zero g_acc and g_bcnt.
// ---------------------------------------------------------------------------
__global__ void prep_kernel(const float* __restrict__ x) {
    __shared__ float tile[32][33];
    const int n0 = blockIdx.x * 32;
    const int b0 = blockIdx.y * 32;
    const int tx = threadIdx.x, ty = threadIdx.y;

    tile[ty][tx] = x[(b0 + ty) * NB_N + (n0 + tx)];

    if (blockIdx.y == 0 && ty == 0 && (n0 + tx) < NBUCK) g_bcnt[n0 + tx] = 0;
    __syncthreads();

    const int idx = (n0 + ty) * NB_B + (b0 + tx);
    g_xT[idx] = tile[tx][ty];
    g_acc[idx] = 0.0f;
}

// ---------------------------------------------------------------------------
// Kernel 2: coarse partition of edges into NBUCK src-range buckets.
// Block-aggregated: smem histogram -> ONE global atomicAdd per (block,bucket)
// -> smem-cursor placement. Fixed BUCK_CAP stride, so no scan pass needed.
// ---------------------------------------------------------------------------
#define PART_T 512
#define PART_EPT 8
#define PART_EPB (PART_T * PART_EPT)   // 4096 edges/block
__global__ void part_kernel(const float* __restrict__ adj,
                            const float* __restrict__ w,
                            const int*   __restrict__ src,
                            const int*   __restrict__ dst) {
    __shared__ int sh_base[NBUCK];
    __shared__ int sh_cur[NBUCK];
    const int t = threadIdx.x;

    if (t < NBUCK) sh_cur[t] = 0;   // histogram phase uses sh_cur
    __syncthreads();

    const int e0 = blockIdx.x * PART_EPB + t;
    int   key[PART_EPT];
    float cf[PART_EPT];
    int   bk[PART_EPT];

    #pragma unroll
    for (int i = 0; i < PART_EPT; i++) {
        const int e = e0 + i * PART_T;
        bk[i] = -1;
        if (e < NB_E) {
            const int s = src[e];
            const int d = dst[e];
            key[i] = (s << 15) | d;              // s < 32768, d < 32768
            cf[i]  = adj[e] * w[e];
            bk[i]  = s >> BUCK_SHIFT;
            atomicAdd(&sh_cur[bk[i]], 1);
        }
    }
    __syncthreads();

    if (t < NBUCK) {
        sh_base[t] = atomicAdd(&g_bcnt[t], sh_cur[t]);  // reserve region
        sh_cur[t] = 0;
    }
    __syncthreads();

    #pragma unroll
    for (int i = 0; i < PART_EPT; i++) {
        if (bk[i] >= 0) {
            const int pos = sh_base[bk[i]] + atomicAdd(&sh_cur[bk[i]], 1);
            g_ebuf[bk[i] * BUCK_CAP + pos] = make_int2(key[i], __float_as_int(cf[i]));
        }
    }
}

// ---------------------------------------------------------------------------
// Kernel 3: edge scatter with L1-resident gathers. Half-warp (16 lanes) per
// edge, float4 gather from the bucket's 32KB xT slice (L1 hit after warmup),
// float4 RED into g_acc[dst]. Grid = (bucket, split).
// ---------------------------------------------------------------------------
#define P2_T 512
#define P2_SPLITS 3
__global__ void edge2_kernel() {
    const int k   = blockIdx.x;
    const int cnt = g_bcnt[k];
    const int chunk = (cnt + P2_SPLITS - 1) / P2_SPLITS;
    const int lo = blockIdx.y * chunk;
    const int hi = min(cnt, lo + chunk);

    const int2* __restrict__ base = g_ebuf + (size_t)k * BUCK_CAP;
    const int hw = threadIdx.x >> 4;    // 0..31 half-warps
    const int l4 = threadIdx.x & 15;    // float4 lane

    int i = lo + hw;
    for (; i + 32 < hi; i += 64) {      // 2-deep software pipeline for MLP
        const int2 e0 = base[i];
        const int2 e1 = base[i + 32];

        const int   s0 = e0.x >> 15, d0 = e0.x & 0x7fff;
        const float c0 = __int_as_float(e0.y);
        const float4 v0 = *((const float4*)(g_xT + (size_t)s0 * NB_B) + l4);

        const int   s1 = e1.x >> 15, d1 = e1.x & 0x7fff;
        const float c1 = __int_as_float(e1.y);
        const float4 v1 = *((const float4*)(g_xT + (size_t)s1 * NB_B) + l4);

        atomicAdd((float4*)(g_acc + (size_t)d0 * NB_B) + l4,
                  make_float4(c0 * v0.x, c0 * v0.y, c0 * v0.z, c0 * v0.w));
        atomicAdd((float4*)(g_acc + (size_t)d1 * NB_B) + l4,
                  make_float4(c1 * v1.x, c1 * v1.y, c1 * v1.z, c1 * v1.w));
    }
    for (; i < hi; i += 32) {
        const int2 e = base[i];
        const int   s = e.x >> 15, d = e.x & 0x7fff;
        const float c = __int_as_float(e.y);
        const float4 v = *((const float4*)(g_xT + (size_t)s * NB_B) + l4);
        atomicAdd((float4*)(g_acc + (size_t)d * NB_B) + l4,
                  make_float4(c * v.x, c * v.y, c * v.z, c * v.w));
    }
}

// ---------------------------------------------------------------------------
// Kernel 4: epilogue. Transpose g_acc [N, B] -> out [B, N] while applying
//   out[b][n] = relu(acc[n][b] * (x[0][n] * self_w[n]) + bias[n])
// ---------------------------------------------------------------------------
__global__ void epilogue_kernel(const float* __restrict__ x,
                                const float* __restrict__ self_w,
                                const float* __restrict__ bias,
                                float* __restrict__ out) {
    __shared__ float tile[32][33];
    const int n0 = blockIdx.x * 32;
    const int b0 = blockIdx.y * 32;
    const int tx = threadIdx.x, ty = threadIdx.y;

    tile[ty][tx] = g_acc[(n0 + ty) * NB_B + (b0 + tx)];
    __syncthreads();

    const int n = n0 + tx;
    const float sl = x[n] * self_w[n];   // x row 0 (faithful reference quirk)
    const float o  = tile[tx][ty] * sl + bias[n];
    out[(b0 + ty) * NB_N + n] = fmaxf(o, 0.0f);
}

// ---------------------------------------------------------------------------
// Launch
// ---------------------------------------------------------------------------
extern "C" void kernel_launch(void* const* d_in, const int* in_sizes, int n_in,
                              void* d_out, int out_size) {
    const float* x      = (const float*)d_in[0];
    const float* adj    = (const float*)d_in[1];
    const float* w      = (const float*)d_in[2];
    const float* self_w = (const float*)d_in[3];
    const float* bias   = (const float*)d_in[4];
    const int*   src    = (const int*)d_in[5];
    const int*   dst    = (const int*)d_in[6];
    float* out = (float*)d_out;

    dim3 tb(32, 32);
    dim3 tg(NB_N / 32, NB_B / 32);   // (625, 2)
    prep_kernel<<<tg, tb>>>(x);

    const int pgrid = (NB_E + PART_EPB - 1) / PART_EPB;   // 313
    part_kernel<<<pgrid, PART_T>>>(adj, w, src, dst);

    edge2_kernel<<<dim3(NBUCK, P2_SPLITS), P2_T>>>();

    epilogue_kernel<<<tg, tb>>>(x, self_w, bias, out);
}